// round 2
// baseline (speedup 1.0000x reference)
#include <cuda_runtime.h>
#include <math.h>

typedef unsigned long long u64;

static constexpr int Hh  = 96;
static constexpr int Ww  = 96;
static constexpr int HW  = 96 * 96;      // 9216
static constexpr int CIN = 64;
static constexpr int CO  = 128;
static constexpr int NB  = 8;

// Scratch for intermediate offset / mask maps (no cudaMalloc allowed).
__device__ float g_off [NB * 18 * HW];   // [b][2*tap(+dy,dx)][pix]
__device__ float g_mask[NB *  9 * HW];   // [b][tap][pix] (post-sigmoid)

__device__ __forceinline__ u64 pk2(float lo, float hi) {
    u64 r; asm("mov.b64 %0, {%1, %2};" : "=l"(r) : "f"(lo), "f"(hi)); return r;
}
__device__ __forceinline__ void upk2(u64 v, float& lo, float& hi) {
    asm("mov.b64 {%0, %1}, %2;" : "=f"(lo), "=f"(hi) : "l"(v));
}
__device__ __forceinline__ void ffma2(u64& d, u64 a, u64 b) {
    asm("fma.rn.f32x2 %0, %1, %2, %0;" : "+l"(d) : "l"(a), "l"(b));
}

// ---------------------------------------------------------------------------
// Kernel 1: offset (18ch) + mask (9ch, sigmoid) 3x3 conv, stride 1 pad 1.
// Block: 16x16 spatial tile, one batch. smem: x tile [64][18][18] + weights
// ws[576][28] (27 outputs padded to 28 so pairs load as LDS.128).
// Accumulators packed as 14 x f32x2 (full-rate FFMA2).
// ---------------------------------------------------------------------------
__global__ __launch_bounds__(256, 1) void k_offmask(
    const float* __restrict__ x,  const float* __restrict__ ow,
    const float* __restrict__ ob, const float* __restrict__ mw,
    const float* __restrict__ mb)
{
    extern __shared__ float sm1[];
    float* sx = sm1;                 // 64*324 = 20736 floats
    float* ws = sm1 + 20736;         // 576*28 = 16128 floats

    const int tid = threadIdx.x;
    const int b   = blockIdx.y;
    const int ty0 = (blockIdx.x / 6) * 16;
    const int tx0 = (blockIdx.x % 6) * 16;

    // weights: ws[c*9+t][j], j in 0..26 (18 offset + 9 mask), pad j=27 to 0.
    for (int i = tid; i < 576 * 27; i += 256) {
        int ct = i / 27, j = i % 27;
        ws[ct * 28 + j] = (j < 18) ? ow[j * 576 + ct] : mw[(j - 18) * 576 + ct];
    }
    for (int i = tid; i < 576; i += 256) ws[i * 28 + 27] = 0.f;

    // x tile with halo (18x18 per channel), zero padded.
    const float* xb = x + b * CIN * HW;
    for (int i = tid; i < CIN * 324; i += 256) {
        int c = i / 324, r = (i % 324) / 18, cc = i % 18;
        int gy = ty0 - 1 + r, gx = tx0 - 1 + cc;
        sx[i] = ((unsigned)gy < (unsigned)Hh && (unsigned)gx < (unsigned)Ww)
                  ? xb[c * HW + gy * Ww + gx] : 0.f;
    }
    __syncthreads();

    const int px = tid & 15, py = tid >> 4;

    u64 acc[14];
    #pragma unroll
    for (int q = 0; q < 14; ++q) {
        int j0 = 2 * q, j1 = 2 * q + 1;
        float lo = (j0 < 18) ? ob[j0] : mb[j0 - 18];
        float hi = (j1 < 18) ? ob[j1] : ((j1 < 27) ? mb[j1 - 18] : 0.f);
        acc[q] = pk2(lo, hi);
    }

    for (int c = 0; c < CIN; ++c) {
        const float* sc = sx + c * 324 + py * 18 + px;
        const float* wc = ws + c * 9 * 28;
        #pragma unroll
        for (int t = 0; t < 9; ++t) {
            float v = sc[(t / 3) * 18 + (t % 3)];
            u64 vs = pk2(v, v);
            const ulonglong2* wp = (const ulonglong2*)(wc + t * 28);
            #pragma unroll
            for (int q = 0; q < 7; ++q) {
                ulonglong2 w2 = wp[q];
                ffma2(acc[2 * q],     w2.x, vs);
                ffma2(acc[2 * q + 1], w2.y, vs);
            }
        }
    }

    float accf[28];
    #pragma unroll
    for (int q = 0; q < 14; ++q) upk2(acc[q], accf[2 * q], accf[2 * q + 1]);

    const int pix = (ty0 + py) * Ww + tx0 + px;
    float* op = g_off + b * 18 * HW + pix;
    #pragma unroll
    for (int j = 0; j < 18; ++j) op[j * HW] = accf[j];
    float* mp = g_mask + b * 9 * HW + pix;
    #pragma unroll
    for (int j = 0; j < 9; ++j) mp[j * HW] = 1.f / (1.f + __expf(-accf[18 + j]));
}

// ---------------------------------------------------------------------------
// Kernel 2: fused bilinear im2col (modulated) + [128 x 576] GEMM.
// Block: 32 pixels of one batch image. Phase 1 builds cols[576][32] in smem
// (warp = 32 lanes = 32 consecutive pixels -> coalesced gathers; each warp
// covers 8 input channels). Phase 2: 576-k GEMM, weight chunk staged
// transposed into smem [kk][o] (pad 144 -> 2-way STS conflicts, 16B aligned),
// thread computes 8 o x 2 px, o-pair-packed FFMA2.
// ---------------------------------------------------------------------------
__global__ __launch_bounds__(256, 2) void k_deform(
    const float* __restrict__ x, const float* __restrict__ wgt,
    const float* __restrict__ bias, float* __restrict__ out)
{
    extern __shared__ float sm2[];
    float* cols = sm2;               // 576*32 = 18432 floats
    float* wbuf = sm2 + 18432;       // 64*144 =  9216 floats

    const int tid  = threadIdx.x;
    const int b    = blockIdx.y;
    const int base = blockIdx.x * 32;
    const int lane = tid & 31, warp = tid >> 5;

    // ---- phase 1: bilinear im2col ----
    {
        const int p  = base + lane;
        const int ho = p / Ww, wo = p % Ww;
        const float* xb   = x + b * CIN * HW;
        const float* offp = g_off  + b * 18 * HW + p;
        const float* mskp = g_mask + b *  9 * HW + p;
        const int c0 = warp * 8;
        #pragma unroll
        for (int t = 0; t < 9; ++t) {
            float dy = offp[(2 * t) * HW];
            float dx = offp[(2 * t + 1) * HW];
            float m  = mskp[t * HW];
            float fy = (float)(ho - 1 + t / 3) + dy;
            float fx = (float)(wo - 1 + t % 3) + dx;
            float y0f = floorf(fy), x0f = floorf(fx);
            int y0 = (int)y0f, x0 = (int)x0f;
            float ly = fy - y0f, lx = fx - x0f;
            float hy = 1.f - ly, hx = 1.f - lx;
            float w00 = hy * hx * m, w01 = hy * lx * m;
            float w10 = ly * hx * m, w11 = ly * lx * m;
            // zero-pad bilinear: out-of-range corner contributes 0
            bool vy0 = (y0 >= 0)  & (y0 <= Hh - 1);
            bool vy1 = (y0 >= -1) & (y0 <= Hh - 2);
            bool vx0 = (x0 >= 0)  & (x0 <= Ww - 1);
            bool vx1 = (x0 >= -1) & (x0 <= Ww - 2);
            if (!(vy0 && vx0)) w00 = 0.f;
            if (!(vy0 && vx1)) w01 = 0.f;
            if (!(vy1 && vx0)) w10 = 0.f;
            if (!(vy1 && vx1)) w11 = 0.f;
            int iy0 = min(max(y0, 0),     Hh - 1);
            int iy1 = min(max(y0 + 1, 0), Hh - 1);
            int ix0 = min(max(x0, 0),     Ww - 1);
            int ix1 = min(max(x0 + 1, 0), Ww - 1);
            int i00 = iy0 * Ww + ix0, i01 = iy0 * Ww + ix1;
            int i10 = iy1 * Ww + ix0, i11 = iy1 * Ww + ix1;
            #pragma unroll
            for (int ci = 0; ci < 8; ++ci) {
                const float* xc = xb + (c0 + ci) * HW;
                float v = w00 * xc[i00] + w01 * xc[i01]
                        + w10 * xc[i10] + w11 * xc[i11];
                cols[((c0 + ci) * 9 + t) * 32 + lane] = v;
            }
        }
    }

    // ---- phase 2: GEMM out[128][32] ----
    const int tx = tid & 15, ty = tid >> 4;   // tx: px pair, ty: o octet
    u64 acc[4][2];
    #pragma unroll
    for (int j = 0; j < 4; ++j) { acc[j][0] = 0ull; acc[j][1] = 0ull; }

    for (int k0 = 0; k0 < 576; k0 += 64) {
        __syncthreads();   // cols ready (1st iter) / prev chunk consumed
        #pragma unroll 8
        for (int i = tid; i < 64 * 128; i += 256) {
            int o = i >> 6, kk = i & 63;
            wbuf[kk * 144 + o] = wgt[o * 576 + k0 + kk];
        }
        __syncthreads();
        const float* wrow = wbuf + ty * 8;
        const float* crow = cols + k0 * 32 + tx * 2;
        #pragma unroll 16
        for (int kk = 0; kk < 64; ++kk) {
            float2 cc = *(const float2*)(crow + kk * 32);
            u64 s0 = pk2(cc.x, cc.x);
            u64 s1 = pk2(cc.y, cc.y);
            ulonglong2 wA = *(const ulonglong2*)(wrow + kk * 144);
            ulonglong2 wB = *(const ulonglong2*)(wrow + kk * 144 + 4);
            ffma2(acc[0][0], wA.x, s0); ffma2(acc[0][1], wA.x, s1);
            ffma2(acc[1][0], wA.y, s0); ffma2(acc[1][1], wA.y, s1);
            ffma2(acc[2][0], wB.x, s0); ffma2(acc[2][1], wB.x, s1);
            ffma2(acc[3][0], wB.y, s0); ffma2(acc[3][1], wB.y, s1);
        }
    }

    float* outp = out + (size_t)(b * CO) * HW + base + tx * 2;
    #pragma unroll
    for (int j = 0; j < 4; ++j) {
        int o = ty * 8 + j * 2;
        float e0, d0, e1, d1;
        upk2(acc[j][0], e0, d0);   // px0: values for (o, o+1)
        upk2(acc[j][1], e1, d1);   // px1: values for (o, o+1)
        float be = bias[o], bo = bias[o + 1];
        *(float2*)(outp + (size_t)o       * HW) = make_float2(e0 + be, e1 + be);
        *(float2*)(outp + (size_t)(o + 1) * HW) = make_float2(d0 + bo, d1 + bo);
    }
}

// ---------------------------------------------------------------------------
extern "C" void kernel_launch(void* const* d_in, const int* in_sizes, int n_in,
                              void* d_out, int out_size)
{
    const float* x   = (const float*)d_in[0];   // [8,64,96,96]
    const float* ow  = (const float*)d_in[1];   // [18,64,3,3]
    const float* ob  = (const float*)d_in[2];   // [18]
    const float* mw  = (const float*)d_in[3];   // [9,64,3,3]
    const float* mb  = (const float*)d_in[4];   // [9]
    const float* wgt = (const float*)d_in[5];   // [128,64,3,3]
    const float* bs  = (const float*)d_in[6];   // [128]
    float* out = (float*)d_out;                 // [8,128,96,96]

    cudaFuncSetAttribute(k_offmask, cudaFuncAttributeMaxDynamicSharedMemorySize, 147456);
    cudaFuncSetAttribute(k_deform,  cudaFuncAttributeMaxDynamicSharedMemorySize, 110592);

    k_offmask<<<dim3(36, 8),  256, 147456>>>(x, ow, ob, mw, mb);
    k_deform <<<dim3(288, 8), 256, 110592>>>(x, wgt, bs, out);
}

// round 4
// speedup vs baseline: 3.1400x; 3.1400x over previous
#include <cuda_runtime.h>
#include <cuda_bf16.h>
#include <math.h>
#include <stdint.h>

typedef unsigned long long u64;

static constexpr int Hh  = 96;
static constexpr int Ww  = 96;
static constexpr int HW  = 96 * 96;      // 9216
static constexpr int CIN = 64;
static constexpr int CO  = 128;
static constexpr int NB  = 8;

// Scratch (no cudaMalloc allowed).
__device__ float g_off [NB * 18 * HW];          // [b][2*tap(dy,dx)][pix]
__device__ float g_mask[NB *  9 * HW];          // [b][tap][pix] post-sigmoid
__device__ float g_xt  [NB * HW * CIN];         // x transposed: [b][hw][c]
__device__ __nv_bfloat16 g_whi[9 * 8192];       // per-tap pre-swizzled bf16 hi
__device__ __nv_bfloat16 g_wlo[9 * 8192];       // per-tap pre-swizzled bf16 lo

__device__ __forceinline__ u64 pk2(float lo, float hi) {
    u64 r; asm("mov.b64 %0, {%1, %2};" : "=l"(r) : "f"(lo), "f"(hi)); return r;
}
__device__ __forceinline__ void upk2(u64 v, float& lo, float& hi) {
    asm("mov.b64 {%0, %1}, %2;" : "=f"(lo), "=f"(hi) : "l"(v));
}
__device__ __forceinline__ void ffma2(u64& d, u64 a, u64 b) {
    asm("fma.rn.f32x2 %0, %1, %2, %0;" : "+l"(d) : "l"(a), "l"(b));
}
__device__ __forceinline__ int swz(int off) { return off ^ ((off >> 3) & 0x70); }
__device__ __forceinline__ uint32_t smem_u32(const void* p) {
    uint32_t a;
    asm("{ .reg .u64 t; cvta.to.shared.u64 t, %1; cvt.u32.u64 %0, t; }" : "=r"(a) : "l"(p));
    return a;
}
__device__ __forceinline__ uint32_t pkbf(float a, float b) {
    __nv_bfloat162 t = __floats2bfloat162_rn(a, b);   // .x = a (low half)
    return *(uint32_t*)&t;
}
__device__ __forceinline__ void ldsm4(uint32_t* r, uint32_t a) {
    asm volatile("ldmatrix.sync.aligned.m8n8.x4.shared.b16 {%0,%1,%2,%3}, [%4];"
        : "=r"(r[0]), "=r"(r[1]), "=r"(r[2]), "=r"(r[3]) : "r"(a));
}
__device__ __forceinline__ void mma_bf16(float* d, const uint32_t* a,
                                         uint32_t b0, uint32_t b1) {
    asm volatile("mma.sync.aligned.m16n8k16.row.col.f32.bf16.bf16.f32 "
        "{%0,%1,%2,%3}, {%4,%5,%6,%7}, {%8,%9}, {%0,%1,%2,%3};"
        : "+f"(d[0]), "+f"(d[1]), "+f"(d[2]), "+f"(d[3])
        : "r"(a[0]), "r"(a[1]), "r"(a[2]), "r"(a[3]), "r"(b0), "r"(b1));
}

// ---------------------------------------------------------------------------
// Kernel W: split main-conv weights into bf16 hi/lo, k' = tap*64 + c order,
// pre-swizzled per tap chunk (row o: 64 bf16 = 128B, SW128 XOR swizzle).
// ---------------------------------------------------------------------------
__global__ void k_wprep(const float* __restrict__ wgt) {
    int i = blockIdx.x * 256 + threadIdx.x;      // 128*576
    if (i >= 128 * 576) return;
    int o = i / 576, r = i % 576;
    int t = r / 64, c = r % 64;
    float v = wgt[o * 576 + c * 9 + t];
    __nv_bfloat16 h = __float2bfloat16(v);
    float lo = v - __bfloat162float(h);
    int sw = swz(o * 128 + c * 2) >> 1;
    g_whi[t * 8192 + sw] = h;
    g_wlo[t * 8192 + sw] = __float2bfloat16(lo);
}

// ---------------------------------------------------------------------------
// Kernel X: transpose x[b][c][hw] -> g_xt[b][hw][c]  (channels contiguous).
// ---------------------------------------------------------------------------
__global__ __launch_bounds__(256) void k_xt(const float* __restrict__ x) {
    __shared__ float t[32][33];
    const int b = blockIdx.z, c0 = blockIdx.y * 32, hw0 = blockIdx.x * 32;
    const int lx = threadIdx.x & 31, ly = threadIdx.x >> 5;
    const float* xb = x + (size_t)b * CIN * HW;
    #pragma unroll
    for (int j = ly; j < 32; j += 8)
        t[j][lx] = xb[(c0 + j) * HW + hw0 + lx];
    __syncthreads();
    float* xt = g_xt + (size_t)b * HW * CIN;
    #pragma unroll
    for (int j = ly; j < 32; j += 8)
        xt[(hw0 + j) * CIN + c0 + lx] = t[lx][j];
}

// ---------------------------------------------------------------------------
// Kernel 1: offset (18ch) + mask (9ch, sigmoid) 3x3 conv (unchanged design).
// ---------------------------------------------------------------------------
__global__ __launch_bounds__(256, 1) void k_offmask(
    const float* __restrict__ x,  const float* __restrict__ ow,
    const float* __restrict__ ob, const float* __restrict__ mw,
    const float* __restrict__ mb)
{
    extern __shared__ float sm1[];
    float* sx = sm1;                 // 64*324 floats
    float* ws = sm1 + 20736;         // 576*28 floats

    const int tid = threadIdx.x;
    const int b   = blockIdx.y;
    const int ty0 = (blockIdx.x / 6) * 16;
    const int tx0 = (blockIdx.x % 6) * 16;

    for (int i = tid; i < 576 * 27; i += 256) {
        int ct = i / 27, j = i % 27;
        ws[ct * 28 + j] = (j < 18) ? ow[j * 576 + ct] : mw[(j - 18) * 576 + ct];
    }
    for (int i = tid; i < 576; i += 256) ws[i * 28 + 27] = 0.f;

    const float* xb = x + b * CIN * HW;
    for (int i = tid; i < CIN * 324; i += 256) {
        int c = i / 324, r = (i % 324) / 18, cc = i % 18;
        int gy = ty0 - 1 + r, gx = tx0 - 1 + cc;
        sx[i] = ((unsigned)gy < (unsigned)Hh && (unsigned)gx < (unsigned)Ww)
                  ? xb[c * HW + gy * Ww + gx] : 0.f;
    }
    __syncthreads();

    const int px = tid & 15, py = tid >> 4;

    u64 acc[14];
    #pragma unroll
    for (int q = 0; q < 14; ++q) {
        int j0 = 2 * q, j1 = 2 * q + 1;
        float lo = (j0 < 18) ? ob[j0] : mb[j0 - 18];
        float hi = (j1 < 18) ? ob[j1] : ((j1 < 27) ? mb[j1 - 18] : 0.f);
        acc[q] = pk2(lo, hi);
    }

    for (int c = 0; c < CIN; ++c) {
        const float* sc = sx + c * 324 + py * 18 + px;
        const float* wc = ws + c * 9 * 28;
        #pragma unroll
        for (int t = 0; t < 9; ++t) {
            float v = sc[(t / 3) * 18 + (t % 3)];
            u64 vs = pk2(v, v);
            const ulonglong2* wp = (const ulonglong2*)(wc + t * 28);
            #pragma unroll
            for (int q = 0; q < 7; ++q) {
                ulonglong2 w2 = wp[q];
                ffma2(acc[2 * q],     w2.x, vs);
                ffma2(acc[2 * q + 1], w2.y, vs);
            }
        }
    }

    float accf[28];
    #pragma unroll
    for (int q = 0; q < 14; ++q) upk2(acc[q], accf[2 * q], accf[2 * q + 1]);

    const int pix = (ty0 + py) * Ww + tx0 + px;
    float* op = g_off + b * 18 * HW + pix;
    #pragma unroll
    for (int j = 0; j < 18; ++j) op[j * HW] = accf[j];
    float* mp = g_mask + b * 9 * HW + pix;
    #pragma unroll
    for (int j = 0; j < 9; ++j) mp[j * HW] = 1.f / (1.f + __expf(-accf[18 + j]));
}

// ---------------------------------------------------------------------------
// Kernel 2: fused bilinear im2col + mma.sync bf16 3-split GEMM.
// Block: 128 px of one image, out tile [128 o][128 px], K'=576 (tap-major).
// Chunk ch = tap ch: A [128 o][64 c] hi/lo, B [128 px][64 c] hi/lo (SW128
// XOR swizzle, built via x_t channel-quad LDG.128 gathers + separable
// bilinear weights from a per-block tap table). 8 warps: warp_m in 0..3
// (32 o), warp_n in 0..1 (64 px); mma m16n8k16, 3 splits (hh, hl, lh).
// SMEM: tap 0..36864 | A_hi 36864 | A_lo 53248 | B_hi 69632 | B_lo 86016
//       total 102400 (2 CTAs/SM).
// ---------------------------------------------------------------------------
static constexpr int SM_TAP   = 0;
static constexpr int SM_AHI   = 36864;
static constexpr int SM_ALO   = 53248;
static constexpr int SM_BHI   = 69632;
static constexpr int SM_BLO   = 86016;
static constexpr int SM_TOTAL = 102400;

__global__ __launch_bounds__(256, 2) void k_deform(
    const float* __restrict__ bias, float* __restrict__ out)
{
    extern __shared__ __align__(128) char smemc[];
    const uint32_t smem_base = smem_u32(smemc);
    const int tid  = threadIdx.x;
    const int wid  = tid >> 5, lane = tid & 31;
    const int b    = blockIdx.y;
    const int base = blockIdx.x * 128;

    // ---- phase 0: per-pixel separable tap table (9 taps x 128 px) ----
    {
        const float* offb = g_off  + b * 18 * HW;
        const float* mskb = g_mask + b *  9 * HW;
        for (int i = tid; i < 128 * 9; i += 256) {
            int pxl = i / 9, t = i % 9;
            int p = base + pxl;
            int ho = p / Ww, wo = p - ho * Ww;
            float dy = offb[(2 * t) * HW + p];
            float dx = offb[(2 * t + 1) * HW + p];
            float m  = mskb[t * HW + p];
            float fy = (float)(ho - 1 + t / 3) + dy;
            float fx = (float)(wo - 1 + t % 3) + dx;
            float y0f = floorf(fy), x0f = floorf(fx);
            int y0 = (int)y0f, x0 = (int)x0f;
            float ly = fy - y0f, lx = fx - x0f;
            float hy = 1.f - ly, hx = 1.f - lx;
            // separable row/col weights over the loaded 2x2 window,
            // with zero-pad edge remap matching the reference exactly.
            float rwA = 0.f, rwB = 0.f, cwA = 0.f, cwB = 0.f;
            if (y0 >= 0 && y0 <= Hh - 2)      { rwA = hy; rwB = ly; }
            else if (y0 == -1)                { rwA = ly; }
            else if (y0 == Hh - 1)            { rwB = hy; }
            if (x0 >= 0 && x0 <= Ww - 2)      { cwA = hx; cwB = lx; }
            else if (x0 == -1)                { cwA = lx; }
            else if (x0 == Ww - 1)            { cwB = hx; }
            rwA *= m; rwB *= m;
            int by = min(max(y0, 0), Hh - 2);
            int bx = min(max(x0, 0), Ww - 2);
            int offA = (by * Ww + bx) * CIN;
            float4* tp = (float4*)(smemc + SM_TAP + i * 32);
            tp[0] = make_float4(rwA, rwB, cwA, cwB);
            tp[1] = make_float4(__int_as_float(offA), 0.f, 0.f, 0.f);
        }
    }

    // per-thread ldmatrix address constants
    const int warp_m = wid & 3, warp_n = wid >> 2;
    const int lr = lane & 15, gk = lane >> 4;           // gk in {0,1}
    const int aRow = warp_m * 32 + lr;
    const int bRow = warp_n * 64 + lr;
    uint32_t aoff[4], boff[4];
    #pragma unroll
    for (int ks = 0; ks < 4; ++ks) {
        aoff[ks] = aRow * 128 + (((2 * ks + gk) ^ (aRow & 7)) << 4);
        boff[ks] = bRow * 128 + (((2 * ks + gk) ^ (bRow & 7)) << 4);
    }

    float acc[64];
    #pragma unroll
    for (int i = 0; i < 64; ++i) acc[i] = 0.f;

    const float* xtb = g_xt + (size_t)b * HW * CIN;

    for (int ch = 0; ch < 9; ++ch) {
        __syncthreads();   // previous chunk's ldmatrix reads complete
        // stage pre-swizzled weights (straight vector copy)
        {
            const float4* ghi = (const float4*)(g_whi + ch * 8192);
            const float4* glo = (const float4*)(g_wlo + ch * 8192);
            float4* ahi = (float4*)(smemc + SM_AHI);
            float4* alo = (float4*)(smemc + SM_ALO);
            #pragma unroll
            for (int i = tid; i < 1024; i += 256) { ahi[i] = ghi[i]; alo[i] = glo[i]; }
        }
        // im2col for tap ch: item = (px, channel quad)
        #pragma unroll
        for (int it = 0; it < 8; ++it) {
            int i = tid + it * 256;
            int pxl = i >> 4, c0 = (i & 15) * 4;
            const float4* tp = (const float4*)(smemc + SM_TAP + (pxl * 9 + ch) * 32);
            float4 w = tp[0];
            int offA = __float_as_int(tp[1].x);
            const float* pb = xtb + offA + c0;
            float4 p00 = *(const float4*)(pb);
            float4 p01 = *(const float4*)(pb + CIN);
            float4 p10 = *(const float4*)(pb + Ww * CIN);
            float4 p11 = *(const float4*)(pb + Ww * CIN + CIN);
            float v0 = w.x * (w.z * p00.x + w.w * p01.x) + w.y * (w.z * p10.x + w.w * p11.x);
            float v1 = w.x * (w.z * p00.y + w.w * p01.y) + w.y * (w.z * p10.y + w.w * p11.y);
            float v2 = w.x * (w.z * p00.z + w.w * p01.z) + w.y * (w.z * p10.z + w.w * p11.z);
            float v3 = w.x * (w.z * p00.w + w.w * p01.w) + w.y * (w.z * p10.w + w.w * p11.w);
            __nv_bfloat16 h0 = __float2bfloat16(v0), h1 = __float2bfloat16(v1);
            __nv_bfloat16 h2 = __float2bfloat16(v2), h3 = __float2bfloat16(v3);
            uint2 hiv, lov;
            hiv.x = pkbf(v0, v1); hiv.y = pkbf(v2, v3);
            // re-pack hi exactly (pkbf re-rounds; force from h*)
            {
                __nv_bfloat162 a; a.x = h0; a.y = h1; hiv.x = *(uint32_t*)&a;
                __nv_bfloat162 c; c.x = h2; c.y = h3; hiv.y = *(uint32_t*)&c;
            }
            lov.x = pkbf(v0 - __bfloat162float(h0), v1 - __bfloat162float(h1));
            lov.y = pkbf(v2 - __bfloat162float(h2), v3 - __bfloat162float(h3));
            int sw = swz(pxl * 128 + c0 * 2);
            *(uint2*)(smemc + SM_BHI + sw) = hiv;
            *(uint2*)(smemc + SM_BLO + sw) = lov;
        }
        __syncthreads();

        // compute: 4 k-steps of 16
        const uint32_t Ahi = smem_base + SM_AHI, Alo = smem_base + SM_ALO;
        const uint32_t Bhi = smem_base + SM_BHI, Blo = smem_base + SM_BLO;
        #pragma unroll
        for (int ks = 0; ks < 4; ++ks) {
            uint32_t ah[2][4], al[2][4];
            ldsm4(ah[0], Ahi + aoff[ks]);
            ldsm4(ah[1], Ahi + aoff[ks] + 2048);
            ldsm4(al[0], Alo + aoff[ks]);
            ldsm4(al[1], Alo + aoff[ks] + 2048);
            #pragma unroll
            for (int nt = 0; nt < 4; ++nt) {
                uint32_t bh[4], bl[4];
                ldsm4(bh, Bhi + boff[ks] + nt * 2048);
                ldsm4(bl, Blo + boff[ks] + nt * 2048);
                #pragma unroll
                for (int mt = 0; mt < 2; ++mt) {
                    float* d0 = acc + (mt * 8 + nt * 2) * 4;
                    float* d1 = d0 + 4;
                    mma_bf16(d0, ah[mt], bh[0], bh[2]);
                    mma_bf16(d1, ah[mt], bh[1], bh[3]);
                    mma_bf16(d0, ah[mt], bl[0], bl[2]);
                    mma_bf16(d1, ah[mt], bl[1], bl[3]);
                    mma_bf16(d0, al[mt], bh[0], bh[2]);
                    mma_bf16(d1, al[mt], bh[1], bh[3]);
                }
            }
        }
    }

    // ---- epilogue: fragment -> gmem float2 stores ----
    const int row  = lane >> 2, colp = (lane & 3) * 2;
    float* outb = out + (size_t)b * CO * HW + base;
    #pragma unroll
    for (int mt = 0; mt < 2; ++mt) {
        int o0 = warp_m * 32 + mt * 16 + row;
        float b0 = bias[o0], b1 = bias[o0 + 8];
        #pragma unroll
        for (int n8 = 0; n8 < 8; ++n8) {
            const float* d = acc + (mt * 8 + n8) * 4;
            int pxo = warp_n * 64 + n8 * 8 + colp;
            *(float2*)(outb + (size_t)o0 * HW + pxo)       = make_float2(d[0] + b0, d[1] + b0);
            *(float2*)(outb + (size_t)(o0 + 8) * HW + pxo) = make_float2(d[2] + b1, d[3] + b1);
        }
    }
}

// ---------------------------------------------------------------------------
extern "C" void kernel_launch(void* const* d_in, const int* in_sizes, int n_in,
                              void* d_out, int out_size)
{
    const float* x   = (const float*)d_in[0];   // [8,64,96,96]
    const float* ow  = (const float*)d_in[1];   // [18,64,3,3]
    const float* ob  = (const float*)d_in[2];   // [18]
    const float* mw  = (const float*)d_in[3];   // [9,64,3,3]
    const float* mb  = (const float*)d_in[4];   // [9]
    const float* wgt = (const float*)d_in[5];   // [128,64,3,3]
    const float* bs  = (const float*)d_in[6];   // [128]
    float* out = (float*)d_out;                 // [8,128,96,96]

    cudaFuncSetAttribute(k_offmask, cudaFuncAttributeMaxDynamicSharedMemorySize, 147456);
    cudaFuncSetAttribute(k_deform,  cudaFuncAttributeMaxDynamicSharedMemorySize, SM_TOTAL);

    k_wprep  <<<288, 256>>>(wgt);
    k_xt     <<<dim3(288, 2, 8), 256>>>(x);
    k_offmask<<<dim3(36, 8), 256, 147456>>>(x, ow, ob, mw, mb);
    k_deform <<<dim3(72, 8), 256, SM_TOTAL>>>(bs, out);
}

// round 5
// speedup vs baseline: 4.3575x; 1.3877x over previous
#include <cuda_runtime.h>
#include <cuda_bf16.h>
#include <math.h>
#include <stdint.h>

typedef unsigned long long u64;

static constexpr int Hh  = 96;
static constexpr int Ww  = 96;
static constexpr int HW  = 96 * 96;      // 9216
static constexpr int CIN = 64;
static constexpr int CO  = 128;
static constexpr int NB  = 8;

// Scratch (no cudaMalloc allowed).
__device__ float g_off [NB * 18 * HW];          // [b][2*tap(dy,dx)][pix]
__device__ float g_mask[NB *  9 * HW];          // [b][tap][pix] post-sigmoid
__device__ float g_xt  [NB * HW * CIN];         // x transposed: [b][hw][c] fp32
__device__ __nv_bfloat16 g_xthi[NB * HW * CIN]; // bf16 hi split of x_t
__device__ __nv_bfloat16 g_xtlo[NB * HW * CIN]; // bf16 lo split of x_t
__device__ __nv_bfloat16 g_whi [9 * 8192];      // main weights: per-tap swizzled hi
__device__ __nv_bfloat16 g_wlo [9 * 8192];      //                              lo
__device__ __nv_bfloat16 g_owhi[9 * 2048];      // off/mask weights [32 pad][64] hi
__device__ __nv_bfloat16 g_owlo[9 * 2048];      //                              lo

__device__ __forceinline__ int swz(int off) { return off ^ ((off >> 3) & 0x70); }
__device__ __forceinline__ uint32_t smem_u32(const void* p) {
    uint32_t a;
    asm("{ .reg .u64 t; cvta.to.shared.u64 t, %1; cvt.u32.u64 %0, t; }" : "=r"(a) : "l"(p));
    return a;
}
__device__ __forceinline__ uint32_t pkbf(float a, float b) {
    __nv_bfloat162 t = __floats2bfloat162_rn(a, b);
    return *(uint32_t*)&t;
}
__device__ __forceinline__ void ldsm4(uint32_t* r, uint32_t a) {
    asm volatile("ldmatrix.sync.aligned.m8n8.x4.shared.b16 {%0,%1,%2,%3}, [%4];"
        : "=r"(r[0]), "=r"(r[1]), "=r"(r[2]), "=r"(r[3]) : "r"(a));
}
__device__ __forceinline__ void mma_bf16(float* d, const uint32_t* a,
                                         uint32_t b0, uint32_t b1) {
    asm volatile("mma.sync.aligned.m16n8k16.row.col.f32.bf16.bf16.f32 "
        "{%0,%1,%2,%3}, {%4,%5,%6,%7}, {%8,%9}, {%0,%1,%2,%3};"
        : "+f"(d[0]), "+f"(d[1]), "+f"(d[2]), "+f"(d[3])
        : "r"(a[0]), "r"(a[1]), "r"(a[2]), "r"(a[3]), "r"(b0), "r"(b1));
}

// ---------------------------------------------------------------------------
// Kernel W: split main-conv weights (tap-major k, SW128 swizzle).
// ---------------------------------------------------------------------------
__global__ void k_wprep(const float* __restrict__ wgt) {
    int i = blockIdx.x * 256 + threadIdx.x;      // 128*576
    if (i >= 128 * 576) return;
    int o = i / 576, r = i % 576;
    int t = r / 64, c = r % 64;
    float v = wgt[o * 576 + c * 9 + t];
    __nv_bfloat16 h = __float2bfloat16(v);
    float lo = v - __bfloat162float(h);
    int sw = swz(o * 128 + c * 2) >> 1;
    g_whi[t * 8192 + sw] = h;
    g_wlo[t * 8192 + sw] = __float2bfloat16(lo);
}

// ---------------------------------------------------------------------------
// Kernel W2: split offset+mask weights into [32 pad o][64 c] per tap.
// Rows 0..17 = offset, 18..26 = mask, 27..31 = zero.
// ---------------------------------------------------------------------------
__global__ void k_wprep2(const float* __restrict__ ow, const float* __restrict__ mw) {
    int i = blockIdx.x * 256 + threadIdx.x;      // 9*32*64 = 18432
    if (i >= 18432) return;
    int t = i / 2048, r = i % 2048;
    int o = r / 64, c = r % 64;
    float v = 0.f;
    if (o < 18)      v = ow[o * 576 + c * 9 + t];
    else if (o < 27) v = mw[(o - 18) * 576 + c * 9 + t];
    __nv_bfloat16 h = __float2bfloat16(v);
    float lo = v - __bfloat162float(h);
    int sw = swz(o * 128 + c * 2) >> 1;
    g_owhi[t * 2048 + sw] = h;
    g_owlo[t * 2048 + sw] = __float2bfloat16(lo);
}

// ---------------------------------------------------------------------------
// Kernel X: transpose x[b][c][hw] -> g_xt[b][hw][c] (fp32) + bf16 hi/lo.
// ---------------------------------------------------------------------------
__global__ __launch_bounds__(256) void k_xt(const float* __restrict__ x) {
    __shared__ float t[32][33];
    const int b = blockIdx.z, c0 = blockIdx.y * 32, hw0 = blockIdx.x * 32;
    const int lx = threadIdx.x & 31, ly = threadIdx.x >> 5;
    const float* xb = x + (size_t)b * CIN * HW;
    #pragma unroll
    for (int j = ly; j < 32; j += 8)
        t[j][lx] = xb[(c0 + j) * HW + hw0 + lx];
    __syncthreads();
    float* xt = g_xt + (size_t)b * HW * CIN;
    __nv_bfloat16* xh = g_xthi + (size_t)b * HW * CIN;
    __nv_bfloat16* xl = g_xtlo + (size_t)b * HW * CIN;
    #pragma unroll
    for (int j = ly; j < 32; j += 8) {
        float v = t[lx][j];
        size_t idx = (size_t)(hw0 + j) * CIN + c0 + lx;
        xt[idx] = v;
        __nv_bfloat16 h = __float2bfloat16(v);
        xh[idx] = h;
        xl[idx] = __float2bfloat16(v - __bfloat162float(h));
    }
}

// ---------------------------------------------------------------------------
// Kernel 1: offset+mask conv via mma (3-split bf16), out tile [32 o][128 px].
// 9 tap-chunks; B rows copied from pre-split x_t at shifted pixels (zero pad).
// smem: A_hi 0 | A_lo 4096 | B_hi 8192 | B_lo 24576 | total 40960 (4 CTAs/SM).
// ---------------------------------------------------------------------------
static constexpr int OM_AHI = 0;
static constexpr int OM_ALO = 4096;
static constexpr int OM_BHI = 8192;
static constexpr int OM_BLO = 24576;
static constexpr int OM_TOTAL = 40960;

__global__ __launch_bounds__(256, 4) void k_offmask(
    const float* __restrict__ ob, const float* __restrict__ mb)
{
    extern __shared__ __align__(128) char smemc[];
    const uint32_t smem_base = smem_u32(smemc);
    const int tid  = threadIdx.x;
    const int wid  = tid >> 5, lane = tid & 31;
    const int b    = blockIdx.y;
    const int base = blockIdx.x * 128;

    const __nv_bfloat16* xh = g_xthi + (size_t)b * HW * CIN;
    const __nv_bfloat16* xl = g_xtlo + (size_t)b * HW * CIN;

    // ldmatrix address constants
    const int lr = lane & 15, gk = lane >> 4;
    uint32_t aoffm[2][4], boff[4];
    #pragma unroll
    for (int mt = 0; mt < 2; ++mt) {
        int aRow = mt * 16 + lr;
        #pragma unroll
        for (int ks = 0; ks < 4; ++ks)
            aoffm[mt][ks] = aRow * 128 + (((2 * ks + gk) ^ (aRow & 7)) << 4);
    }
    {
        int bRow = wid * 16 + lr;
        #pragma unroll
        for (int ks = 0; ks < 4; ++ks)
            boff[ks] = bRow * 128 + (((2 * ks + gk) ^ (bRow & 7)) << 4);
    }

    float acc[2][2][4];
    #pragma unroll
    for (int mt = 0; mt < 2; ++mt)
        #pragma unroll
        for (int nt = 0; nt < 2; ++nt)
            #pragma unroll
            for (int j = 0; j < 4; ++j) acc[mt][nt][j] = 0.f;

    for (int ch = 0; ch < 9; ++ch) {
        __syncthreads();
        // stage A (pre-swizzled, straight copy): 2048 bf16 each = 4KB
        {
            const uint4* gh = (const uint4*)(g_owhi + ch * 2048);
            const uint4* gl = (const uint4*)(g_owlo + ch * 2048);
            if (tid < 256) {  // 256 x 16B = 4KB
                ((uint4*)(smemc + OM_AHI))[tid] = gh[tid];
                ((uint4*)(smemc + OM_ALO))[tid] = gl[tid];
            }
        }
        // B: [128 px][64 c] from x_t shifted by tap (dy,dx), zero-pad borders.
        {
            const int dy = ch / 3 - 1, dx = ch % 3 - 1;
            #pragma unroll
            for (int it = 0; it < 4; ++it) {
                int i = tid + it * 256;         // 1024 items = 128px x 8 chunks
                int pxl = i >> 3, ci = i & 7;   // ci: 16B chunk (8 bf16)
                int p = base + pxl;
                int ho = p / Ww, wo = p - ho * Ww;
                int sy = ho + dy, sx = wo + dx;
                uint4 hv = make_uint4(0, 0, 0, 0), lv = hv;
                if ((unsigned)sy < (unsigned)Hh && (unsigned)sx < (unsigned)Ww) {
                    size_t q = (size_t)(sy * Ww + sx) * CIN + ci * 8;
                    hv = *(const uint4*)(xh + q);
                    lv = *(const uint4*)(xl + q);
                }
                int sw = swz(pxl * 128 + ci * 16);
                *(uint4*)(smemc + OM_BHI + sw) = hv;
                *(uint4*)(smemc + OM_BLO + sw) = lv;
            }
        }
        __syncthreads();

        const uint32_t Ahi = smem_base + OM_AHI, Alo = smem_base + OM_ALO;
        const uint32_t Bhi = smem_base + OM_BHI, Blo = smem_base + OM_BLO;
        #pragma unroll
        for (int ks = 0; ks < 4; ++ks) {
            uint32_t ah[2][4], al[2][4], bh[4], bl[4];
            ldsm4(ah[0], Ahi + aoffm[0][ks]);
            ldsm4(ah[1], Ahi + aoffm[1][ks]);
            ldsm4(al[0], Alo + aoffm[0][ks]);
            ldsm4(al[1], Alo + aoffm[1][ks]);
            ldsm4(bh, Bhi + boff[ks]);
            ldsm4(bl, Blo + boff[ks]);
            #pragma unroll
            for (int mt = 0; mt < 2; ++mt) {
                float* d0 = acc[mt][0];
                float* d1 = acc[mt][1];
                mma_bf16(d0, ah[mt], bh[0], bh[2]);
                mma_bf16(d1, ah[mt], bh[1], bh[3]);
                mma_bf16(d0, ah[mt], bl[0], bl[2]);
                mma_bf16(d1, ah[mt], bl[1], bl[3]);
                mma_bf16(d0, al[mt], bh[0], bh[2]);
                mma_bf16(d1, al[mt], bh[1], bh[3]);
            }
        }
    }

    // epilogue: write offsets (o<18) and sigmoid mask (18<=o<27)
    const int row = lane >> 2, colp = (lane & 3) * 2;
    float* offb = g_off  + (size_t)b * 18 * HW;
    float* mskb = g_mask + (size_t)b *  9 * HW;
    #pragma unroll
    for (int mt = 0; mt < 2; ++mt) {
        #pragma unroll
        for (int nt = 0; nt < 2; ++nt) {
            const float* d = acc[mt][nt];
            int p = base + wid * 16 + nt * 8 + colp;
            #pragma unroll
            for (int half = 0; half < 2; ++half) {
                int o = mt * 16 + half * 8 + row;
                float v0 = d[half * 2], v1 = d[half * 2 + 1];
                if (o < 18) {
                    float bo = ob[o];
                    *(float2*)(offb + (size_t)o * HW + p) = make_float2(v0 + bo, v1 + bo);
                } else if (o < 27) {
                    float bo = mb[o - 18];
                    float s0 = 1.f / (1.f + __expf(-(v0 + bo)));
                    float s1 = 1.f / (1.f + __expf(-(v1 + bo)));
                    *(float2*)(mskb + (size_t)(o - 18) * HW + p) = make_float2(s0, s1);
                }
            }
        }
    }
}

// ---------------------------------------------------------------------------
// Kernel 2: fused bilinear im2col + mma.sync bf16 3-split GEMM (as round 4).
// ---------------------------------------------------------------------------
static constexpr int SM_TAP   = 0;
static constexpr int SM_AHI   = 36864;
static constexpr int SM_ALO   = 53248;
static constexpr int SM_BHI   = 69632;
static constexpr int SM_BLO   = 86016;
static constexpr int SM_TOTAL = 102400;

__global__ __launch_bounds__(256, 2) void k_deform(
    const float* __restrict__ bias, float* __restrict__ out)
{
    extern __shared__ __align__(128) char smemc[];
    const uint32_t smem_base = smem_u32(smemc);
    const int tid  = threadIdx.x;
    const int wid  = tid >> 5, lane = tid & 31;
    const int b    = blockIdx.y;
    const int base = blockIdx.x * 128;

    // ---- phase 0: per-pixel separable tap table (9 taps x 128 px) ----
    {
        const float* offb = g_off  + (size_t)b * 18 * HW;
        const float* mskb = g_mask + (size_t)b *  9 * HW;
        for (int i = tid; i < 128 * 9; i += 256) {
            int pxl = i / 9, t = i % 9;
            int p = base + pxl;
            int ho = p / Ww, wo = p - ho * Ww;
            float dy = offb[(2 * t) * HW + p];
            float dx = offb[(2 * t + 1) * HW + p];
            float m  = mskb[t * HW + p];
            float fy = (float)(ho - 1 + t / 3) + dy;
            float fx = (float)(wo - 1 + t % 3) + dx;
            float y0f = floorf(fy), x0f = floorf(fx);
            int y0 = (int)y0f, x0 = (int)x0f;
            float ly = fy - y0f, lx = fx - x0f;
            float hy = 1.f - ly, hx = 1.f - lx;
            float rwA = 0.f, rwB = 0.f, cwA = 0.f, cwB = 0.f;
            if (y0 >= 0 && y0 <= Hh - 2)      { rwA = hy; rwB = ly; }
            else if (y0 == -1)                { rwA = ly; }
            else if (y0 == Hh - 1)            { rwB = hy; }
            if (x0 >= 0 && x0 <= Ww - 2)      { cwA = hx; cwB = lx; }
            else if (x0 == -1)                { cwA = lx; }
            else if (x0 == Ww - 1)            { cwB = hx; }
            rwA *= m; rwB *= m;
            int by = min(max(y0, 0), Hh - 2);
            int bx = min(max(x0, 0), Ww - 2);
            int offA = (by * Ww + bx) * CIN;
            float4* tp = (float4*)(smemc + SM_TAP + i * 32);
            tp[0] = make_float4(rwA, rwB, cwA, cwB);
            tp[1] = make_float4(__int_as_float(offA), 0.f, 0.f, 0.f);
        }
    }

    const int warp_m = wid & 3, warp_n = wid >> 2;
    const int lr = lane & 15, gk = lane >> 4;
    const int aRow = warp_m * 32 + lr;
    const int bRow = warp_n * 64 + lr;
    uint32_t aoff[4], boff[4];
    #pragma unroll
    for (int ks = 0; ks < 4; ++ks) {
        aoff[ks] = aRow * 128 + (((2 * ks + gk) ^ (aRow & 7)) << 4);
        boff[ks] = bRow * 128 + (((2 * ks + gk) ^ (bRow & 7)) << 4);
    }

    float acc[64];
    #pragma unroll
    for (int i = 0; i < 64; ++i) acc[i] = 0.f;

    const float* xtb = g_xt + (size_t)b * HW * CIN;

    for (int ch = 0; ch < 9; ++ch) {
        __syncthreads();
        {
            const float4* ghi = (const float4*)(g_whi + ch * 8192);
            const float4* glo = (const float4*)(g_wlo + ch * 8192);
            float4* ahi = (float4*)(smemc + SM_AHI);
            float4* alo = (float4*)(smemc + SM_ALO);
            #pragma unroll
            for (int i = tid; i < 1024; i += 256) { ahi[i] = ghi[i]; alo[i] = glo[i]; }
        }
        #pragma unroll
        for (int it = 0; it < 8; ++it) {
            int i = tid + it * 256;
            int pxl = i >> 4, c0 = (i & 15) * 4;
            const float4* tp = (const float4*)(smemc + SM_TAP + (pxl * 9 + ch) * 32);
            float4 w = tp[0];
            int offA = __float_as_int(tp[1].x);
            const float* pb = xtb + offA + c0;
            float4 p00 = *(const float4*)(pb);
            float4 p01 = *(const float4*)(pb + CIN);
            float4 p10 = *(const float4*)(pb + Ww * CIN);
            float4 p11 = *(const float4*)(pb + Ww * CIN + CIN);
            float v0 = w.x * (w.z * p00.x + w.w * p01.x) + w.y * (w.z * p10.x + w.w * p11.x);
            float v1 = w.x * (w.z * p00.y + w.w * p01.y) + w.y * (w.z * p10.y + w.w * p11.y);
            float v2 = w.x * (w.z * p00.z + w.w * p01.z) + w.y * (w.z * p10.z + w.w * p11.z);
            float v3 = w.x * (w.z * p00.w + w.w * p01.w) + w.y * (w.z * p10.w + w.w * p11.w);
            __nv_bfloat16 h0 = __float2bfloat16(v0), h1 = __float2bfloat16(v1);
            __nv_bfloat16 h2 = __float2bfloat16(v2), h3 = __float2bfloat16(v3);
            uint2 hiv, lov;
            { __nv_bfloat162 a; a.x = h0; a.y = h1; hiv.x = *(uint32_t*)&a; }
            { __nv_bfloat162 c; c.x = h2; c.y = h3; hiv.y = *(uint32_t*)&c; }
            lov.x = pkbf(v0 - __bfloat162float(h0), v1 - __bfloat162float(h1));
            lov.y = pkbf(v2 - __bfloat162float(h2), v3 - __bfloat162float(h3));
            int sw = swz(pxl * 128 + c0 * 2);
            *(uint2*)(smemc + SM_BHI + sw) = hiv;
            *(uint2*)(smemc + SM_BLO + sw) = lov;
        }
        __syncthreads();

        const uint32_t Ahi = smem_base + SM_AHI, Alo = smem_base + SM_ALO;
        const uint32_t Bhi = smem_base + SM_BHI, Blo = smem_base + SM_BLO;
        #pragma unroll
        for (int ks = 0; ks < 4; ++ks) {
            uint32_t ah[2][4], al[2][4];
            ldsm4(ah[0], Ahi + aoff[ks]);
            ldsm4(ah[1], Ahi + aoff[ks] + 2048);
            ldsm4(al[0], Alo + aoff[ks]);
            ldsm4(al[1], Alo + aoff[ks] + 2048);
            #pragma unroll
            for (int nt = 0; nt < 4; ++nt) {
                uint32_t bh[4], bl[4];
                ldsm4(bh, Bhi + boff[ks] + nt * 2048);
                ldsm4(bl, Blo + boff[ks] + nt * 2048);
                #pragma unroll
                for (int mt = 0; mt < 2; ++mt) {
                    float* d0 = acc + (mt * 8 + nt * 2) * 4;
                    float* d1 = d0 + 4;
                    mma_bf16(d0, ah[mt], bh[0], bh[2]);
                    mma_bf16(d1, ah[mt], bh[1], bh[3]);
                    mma_bf16(d0, ah[mt], bl[0], bl[2]);
                    mma_bf16(d1, ah[mt], bl[1], bl[3]);
                    mma_bf16(d0, al[mt], bh[0], bh[2]);
                    mma_bf16(d1, al[mt], bh[1], bh[3]);
                }
            }
        }
    }

    const int row  = lane >> 2, colp = (lane & 3) * 2;
    float* outb = out + (size_t)b * CO * HW + base;
    #pragma unroll
    for (int mt = 0; mt < 2; ++mt) {
        int o0 = warp_m * 32 + mt * 16 + row;
        float b0 = bias[o0], b1 = bias[o0 + 8];
        #pragma unroll
        for (int n8 = 0; n8 < 8; ++n8) {
            const float* d = acc + (mt * 8 + n8) * 4;
            int pxo = warp_n * 64 + n8 * 8 + colp;
            *(float2*)(outb + (size_t)o0 * HW + pxo)       = make_float2(d[0] + b0, d[1] + b0);
            *(float2*)(outb + (size_t)(o0 + 8) * HW + pxo) = make_float2(d[2] + b1, d[3] + b1);
        }
    }
}

// ---------------------------------------------------------------------------
extern "C" void kernel_launch(void* const* d_in, const int* in_sizes, int n_in,
                              void* d_out, int out_size)
{
    const float* x   = (const float*)d_in[0];   // [8,64,96,96]
    const float* ow  = (const float*)d_in[1];   // [18,64,3,3]
    const float* ob  = (const float*)d_in[2];   // [18]
    const float* mw  = (const float*)d_in[3];   // [9,64,3,3]
    const float* mb  = (const float*)d_in[4];   // [9]
    const float* wgt = (const float*)d_in[5];   // [128,64,3,3]
    const float* bs  = (const float*)d_in[6];   // [128]
    float* out = (float*)d_out;                 // [8,128,96,96]

    cudaFuncSetAttribute(k_offmask, cudaFuncAttributeMaxDynamicSharedMemorySize, OM_TOTAL);
    cudaFuncSetAttribute(k_deform,  cudaFuncAttributeMaxDynamicSharedMemorySize, SM_TOTAL);

    k_wprep  <<<288, 256>>>(wgt);
    k_wprep2 <<<72, 256>>>(ow, mw);
    k_xt     <<<dim3(288, 2, 8), 256>>>(x);
    k_offmask<<<dim3(72, 8), 256, OM_TOTAL>>>(ob, mb);
    k_deform <<<dim3(72, 8), 256, SM_TOTAL>>>(bs, out);
}

// round 7
// speedup vs baseline: 4.6933x; 1.0770x over previous
#include <cuda_runtime.h>
#include <cuda_bf16.h>
#include <math.h>
#include <stdint.h>

static constexpr int Hh  = 96;
static constexpr int Ww  = 96;
static constexpr int HW  = 96 * 96;      // 9216
static constexpr int CIN = 64;
static constexpr int CO  = 128;
static constexpr int NB  = 8;

// Scratch (no cudaMalloc allowed).
__device__ float g_xt  [NB * HW * CIN];         // x transposed: [b][hw][c] fp32
__device__ __nv_bfloat16 g_xthi[NB * HW * CIN]; // bf16 hi split of x_t
__device__ __nv_bfloat16 g_xtlo[NB * HW * CIN]; // bf16 lo split of x_t
__device__ __nv_bfloat16 g_whi [9 * 8192];      // main weights: per-tap swizzled hi
__device__ __nv_bfloat16 g_wlo [9 * 8192];      //                              lo
__device__ __nv_bfloat16 g_owhi[9 * 2048];      // off/mask weights [32 pad][64] hi
__device__ __nv_bfloat16 g_owlo[9 * 2048];      //                              lo

__device__ __forceinline__ int swz(int off) { return off ^ ((off >> 3) & 0x70); }
__device__ __forceinline__ uint32_t smem_u32(const void* p) {
    uint32_t a;
    asm("{ .reg .u64 t; cvta.to.shared.u64 t, %1; cvt.u32.u64 %0, t; }" : "=r"(a) : "l"(p));
    return a;
}
__device__ __forceinline__ uint32_t pkbf(float a, float b) {
    __nv_bfloat162 t = __floats2bfloat162_rn(a, b);
    return *(uint32_t*)&t;
}
__device__ __forceinline__ void ldsm4(uint32_t* r, uint32_t a) {
    asm volatile("ldmatrix.sync.aligned.m8n8.x4.shared.b16 {%0,%1,%2,%3}, [%4];"
        : "=r"(r[0]), "=r"(r[1]), "=r"(r[2]), "=r"(r[3]) : "r"(a));
}
__device__ __forceinline__ void mma_bf16(float* d, const uint32_t* a,
                                         uint32_t b0, uint32_t b1) {
    asm volatile("mma.sync.aligned.m16n8k16.row.col.f32.bf16.bf16.f32 "
        "{%0,%1,%2,%3}, {%4,%5,%6,%7}, {%8,%9}, {%0,%1,%2,%3};"
        : "+f"(d[0]), "+f"(d[1]), "+f"(d[2]), "+f"(d[3])
        : "r"(a[0]), "r"(a[1]), "r"(a[2]), "r"(a[3]), "r"(b0), "r"(b1));
}
__device__ __forceinline__ void cpasync16(uint32_t dst, const void* src, int srcBytes) {
    asm volatile("cp.async.cg.shared.global [%0], [%1], 16, %2;"
        :: "r"(dst), "l"(src), "r"(srcBytes) : "memory");
}
__device__ __forceinline__ void cpasync_wait_all() {
    asm volatile("cp.async.wait_all;" ::: "memory");
}

// ---------------------------------------------------------------------------
// Kernel W: split main-conv weights (tap-major k, SW128 swizzle).
// ---------------------------------------------------------------------------
__global__ void k_wprep(const float* __restrict__ wgt) {
    int i = blockIdx.x * 256 + threadIdx.x;      // 128*576
    if (i >= 128 * 576) return;
    int o = i / 576, r = i % 576;
    int t = r / 64, c = r % 64;
    float v = wgt[o * 576 + c * 9 + t];
    __nv_bfloat16 h = __float2bfloat16(v);
    float lo = v - __bfloat162float(h);
    int sw = swz(o * 128 + c * 2) >> 1;
    g_whi[t * 8192 + sw] = h;
    g_wlo[t * 8192 + sw] = __float2bfloat16(lo);
}

// ---------------------------------------------------------------------------
// Kernel W2: split offset+mask weights into [32 pad o][64 c] per tap.
// ---------------------------------------------------------------------------
__global__ void k_wprep2(const float* __restrict__ ow, const float* __restrict__ mw) {
    int i = blockIdx.x * 256 + threadIdx.x;      // 9*32*64 = 18432
    if (i >= 18432) return;
    int t = i / 2048, r = i % 2048;
    int o = r / 64, c = r % 64;
    float v = 0.f;
    if (o < 18)      v = ow[o * 576 + c * 9 + t];
    else if (o < 27) v = mw[(o - 18) * 576 + c * 9 + t];
    __nv_bfloat16 h = __float2bfloat16(v);
    float lo = v - __bfloat162float(h);
    int sw = swz(o * 128 + c * 2) >> 1;
    g_owhi[t * 2048 + sw] = h;
    g_owlo[t * 2048 + sw] = __float2bfloat16(lo);
}

// ---------------------------------------------------------------------------
// Kernel X: transpose x[b][c][hw] -> g_xt[b][hw][c] (fp32) + bf16 hi/lo.
// ---------------------------------------------------------------------------
__global__ __launch_bounds__(256) void k_xt(const float* __restrict__ x) {
    __shared__ float t[32][33];
    const int b = blockIdx.z, c0 = blockIdx.y * 32, hw0 = blockIdx.x * 32;
    const int lx = threadIdx.x & 31, ly = threadIdx.x >> 5;
    const float* xb = x + (size_t)b * CIN * HW;
    #pragma unroll
    for (int j = ly; j < 32; j += 8)
        t[j][lx] = xb[(c0 + j) * HW + hw0 + lx];
    __syncthreads();
    float* xt = g_xt + (size_t)b * HW * CIN;
    __nv_bfloat16* xh = g_xthi + (size_t)b * HW * CIN;
    __nv_bfloat16* xl = g_xtlo + (size_t)b * HW * CIN;
    #pragma unroll
    for (int j = ly; j < 32; j += 8) {
        float v = t[lx][j];
        size_t idx = (size_t)(hw0 + j) * CIN + c0 + lx;
        xt[idx] = v;
        __nv_bfloat16 h = __float2bfloat16(v);
        xh[idx] = h;
        xl[idx] = __float2bfloat16(v - __bfloat162float(h));
    }
}

// ---------------------------------------------------------------------------
// Fused kernel: offset/mask conv (mma) -> smem -> tap table -> deform GEMM.
// Block = 128 px of one image, 256 threads, 8 warps, 2 CTAs/SM.
// smem layout (bytes):
//   A_hi 0 | A_lo 16384 | B_hi 32768 | B_lo 49152 |
//   tapW 65536 (float4 x 1152) | tapO 83968 (int x 1152) | om 88576 (27x128 f32)
//   total 102400
// ---------------------------------------------------------------------------
static constexpr int SM_AHI  = 0;
static constexpr int SM_ALO  = 16384;
static constexpr int SM_BHI  = 32768;
static constexpr int SM_BLO  = 49152;
static constexpr int SM_TAPW = 65536;
static constexpr int SM_TAPO = 83968;
static constexpr int SM_OM   = 88576;
static constexpr int SM_TOTAL = 102400;

__global__ __launch_bounds__(256, 2) void k_main(
    const float* __restrict__ ob, const float* __restrict__ mb,
    const float* __restrict__ bias, float* __restrict__ out)
{
    extern __shared__ __align__(128) char smemc[];
    const uint32_t smem_base = smem_u32(smemc);
    const int tid  = threadIdx.x;
    const int wid  = tid >> 5, lane = tid & 31;
    const int b    = blockIdx.y;
    const int base = blockIdx.x * 128;

    const __nv_bfloat16* xh = g_xthi + (size_t)b * HW * CIN;
    const __nv_bfloat16* xl = g_xtlo + (size_t)b * HW * CIN;

    const int lr = lane & 15, gk = lane >> 4;

    // ================= phase 1: offset+mask conv =================
    {
        // ldmatrix address constants (A tile 32x64, B tile 128x64)
        uint32_t aoffm[2][4], boff[4];
        #pragma unroll
        for (int mt = 0; mt < 2; ++mt) {
            int aRow = mt * 16 + lr;
            #pragma unroll
            for (int ks = 0; ks < 4; ++ks)
                aoffm[mt][ks] = aRow * 128 + (((2 * ks + gk) ^ (aRow & 7)) << 4);
        }
        {
            int bRow = wid * 16 + lr;
            #pragma unroll
            for (int ks = 0; ks < 4; ++ks)
                boff[ks] = bRow * 128 + (((2 * ks + gk) ^ (bRow & 7)) << 4);
        }

        float acc[2][2][4];
        #pragma unroll
        for (int mt = 0; mt < 2; ++mt)
            #pragma unroll
            for (int nt = 0; nt < 2; ++nt)
                #pragma unroll
                for (int j = 0; j < 4; ++j) acc[mt][nt][j] = 0.f;

        for (int ch = 0; ch < 9; ++ch) {
            __syncthreads();
            // stage A via cp.async (4KB hi + 4KB lo)
            cpasync16(smem_base + SM_AHI + tid * 16, (const char*)(g_owhi + ch * 2048) + tid * 16, 16);
            cpasync16(smem_base + SM_ALO + tid * 16, (const char*)(g_owlo + ch * 2048) + tid * 16, 16);
            // stage B via cp.async with zfill for zero-pad borders
            {
                const int dy = ch / 3 - 1, dx = ch % 3 - 1;
                #pragma unroll
                for (int it = 0; it < 4; ++it) {
                    int i = tid + it * 256;         // 1024 items = 128px x 8 chunks
                    int pxl = i >> 3, ci = i & 7;
                    int p = base + pxl;
                    int ho = p / Ww, wo = p - ho * Ww;
                    int sy = ho + dy, sx = wo + dx;
                    bool valid = (unsigned)sy < (unsigned)Hh && (unsigned)sx < (unsigned)Ww;
                    int syc = min(max(sy, 0), Hh - 1), sxc = min(max(sx, 0), Ww - 1);
                    size_t q = (size_t)(syc * Ww + sxc) * CIN + ci * 8;
                    int sw = swz(pxl * 128 + ci * 16);
                    int nb = valid ? 16 : 0;
                    cpasync16(smem_base + SM_BHI + sw, xh + q, nb);
                    cpasync16(smem_base + SM_BLO + sw, xl + q, nb);
                }
            }
            cpasync_wait_all();
            __syncthreads();

            const uint32_t Ahi = smem_base + SM_AHI, Alo = smem_base + SM_ALO;
            const uint32_t Bhi = smem_base + SM_BHI, Blo = smem_base + SM_BLO;
            #pragma unroll
            for (int ks = 0; ks < 4; ++ks) {
                uint32_t ah[2][4], al[2][4], bh[4], bl[4];
                ldsm4(ah[0], Ahi + aoffm[0][ks]);
                ldsm4(ah[1], Ahi + aoffm[1][ks]);
                ldsm4(al[0], Alo + aoffm[0][ks]);
                ldsm4(al[1], Alo + aoffm[1][ks]);
                ldsm4(bh, Bhi + boff[ks]);
                ldsm4(bl, Blo + boff[ks]);
                #pragma unroll
                for (int mt = 0; mt < 2; ++mt) {
                    float* d0 = acc[mt][0];
                    float* d1 = acc[mt][1];
                    mma_bf16(d0, ah[mt], bh[0], bh[2]);
                    mma_bf16(d1, ah[mt], bh[1], bh[3]);
                    mma_bf16(d0, ah[mt], bl[0], bl[2]);
                    mma_bf16(d1, ah[mt], bl[1], bl[3]);
                    mma_bf16(d0, al[mt], bh[0], bh[2]);
                    mma_bf16(d1, al[mt], bh[1], bh[3]);
                }
            }
        }
        __syncthreads();   // all mma/ldsm done before writing om

        // epilogue -> smem om[27][128]: offsets (o<18, +bias), mask sigmoid
        float* om = (float*)(smemc + SM_OM);
        const int row = lane >> 2, colp = (lane & 3) * 2;
        #pragma unroll
        for (int mt = 0; mt < 2; ++mt) {
            #pragma unroll
            for (int nt = 0; nt < 2; ++nt) {
                const float* d = acc[mt][nt];
                int p = wid * 16 + nt * 8 + colp;
                #pragma unroll
                for (int half = 0; half < 2; ++half) {
                    int o = mt * 16 + half * 8 + row;
                    float v0 = d[half * 2], v1 = d[half * 2 + 1];
                    if (o < 18) {
                        float bo = ob[o];
                        *(float2*)(om + o * 128 + p) = make_float2(v0 + bo, v1 + bo);
                    } else if (o < 27) {
                        float bo = mb[o - 18];
                        float s0 = 1.f / (1.f + __expf(-(v0 + bo)));
                        float s1 = 1.f / (1.f + __expf(-(v1 + bo)));
                        *(float2*)(om + o * 128 + p) = make_float2(s0, s1);
                    }
                }
            }
        }
    }
    __syncthreads();

    // ================= phase 2: tap table =================
    {
        const float* om = (const float*)(smemc + SM_OM);
        for (int i = tid; i < 128 * 9; i += 256) {
            int pxl = i / 9, t = i % 9;
            int p = base + pxl;
            int ho = p / Ww, wo = p - ho * Ww;
            float dy = om[(2 * t) * 128 + pxl];
            float dx = om[(2 * t + 1) * 128 + pxl];
            float m  = om[(18 + t) * 128 + pxl];
            float fy = (float)(ho - 1 + t / 3) + dy;
            float fx = (float)(wo - 1 + t % 3) + dx;
            float y0f = floorf(fy), x0f = floorf(fx);
            int y0 = (int)y0f, x0 = (int)x0f;
            float ly = fy - y0f, lx = fx - x0f;
            float hy = 1.f - ly, hx = 1.f - lx;
            float rwA = 0.f, rwB = 0.f, cwA = 0.f, cwB = 0.f;
            if (y0 >= 0 && y0 <= Hh - 2)      { rwA = hy; rwB = ly; }
            else if (y0 == -1)                { rwA = ly; }
            else if (y0 == Hh - 1)            { rwB = hy; }
            if (x0 >= 0 && x0 <= Ww - 2)      { cwA = hx; cwB = lx; }
            else if (x0 == -1)                { cwA = lx; }
            else if (x0 == Ww - 1)            { cwB = hx; }
            rwA *= m; rwB *= m;
            int by = min(max(y0, 0), Hh - 2);
            int bx = min(max(x0, 0), Ww - 2);
            ((float4*)(smemc + SM_TAPW))[i] = make_float4(rwA, rwB, cwA, cwB);
            ((int*)(smemc + SM_TAPO))[i] = (by * Ww + bx) * CIN;
        }
    }

    // ================= phase 3: deform GEMM =================
    const int warp_m = wid & 3, warp_n = wid >> 2;
    const int aRow = warp_m * 32 + lr;
    const int bRow = warp_n * 64 + lr;
    uint32_t aoff[4], boff[4];
    #pragma unroll
    for (int ks = 0; ks < 4; ++ks) {
        aoff[ks] = aRow * 128 + (((2 * ks + gk) ^ (aRow & 7)) << 4);
        boff[ks] = bRow * 128 + (((2 * ks + gk) ^ (bRow & 7)) << 4);
    }

    float acc[64];
    #pragma unroll
    for (int i = 0; i < 64; ++i) acc[i] = 0.f;

    const float* xtb = g_xt + (size_t)b * HW * CIN;

    for (int ch = 0; ch < 9; ++ch) {
        __syncthreads();
        // stage A via cp.async (16KB hi + 16KB lo)
        #pragma unroll
        for (int j = 0; j < 4; ++j) {
            int i = tid + j * 256;
            cpasync16(smem_base + SM_AHI + i * 16, (const char*)(g_whi + ch * 8192) + i * 16, 16);
            cpasync16(smem_base + SM_ALO + i * 16, (const char*)(g_wlo + ch * 8192) + i * 16, 16);
        }
        // im2col for tap ch
        #pragma unroll
        for (int it = 0; it < 8; ++it) {
            int i = tid + it * 256;
            int pxl = i >> 4, c0 = (i & 15) * 4;
            int ti = pxl * 9 + ch;
            float4 w = ((const float4*)(smemc + SM_TAPW))[ti];
            int offA = ((const int*)(smemc + SM_TAPO))[ti];
            const float* pb = xtb + offA + c0;
            float4 p00 = *(const float4*)(pb);
            float4 p01 = *(const float4*)(pb + CIN);
            float4 p10 = *(const float4*)(pb + Ww * CIN);
            float4 p11 = *(const float4*)(pb + Ww * CIN + CIN);
            float v0 = w.x * (w.z * p00.x + w.w * p01.x) + w.y * (w.z * p10.x + w.w * p11.x);
            float v1 = w.x * (w.z * p00.y + w.w * p01.y) + w.y * (w.z * p10.y + w.w * p11.y);
            float v2 = w.x * (w.z * p00.z + w.w * p01.z) + w.y * (w.z * p10.z + w.w * p11.z);
            float v3 = w.x * (w.z * p00.w + w.w * p01.w) + w.y * (w.z * p10.w + w.w * p11.w);
            __nv_bfloat16 h0 = __float2bfloat16(v0), h1 = __float2bfloat16(v1);
            __nv_bfloat16 h2 = __float2bfloat16(v2), h3 = __float2bfloat16(v3);
            uint2 hiv, lov;
            { __nv_bfloat162 a; a.x = h0; a.y = h1; hiv.x = *(uint32_t*)&a; }
            { __nv_bfloat162 c; c.x = h2; c.y = h3; hiv.y = *(uint32_t*)&c; }
            lov.x = pkbf(v0 - __bfloat162float(h0), v1 - __bfloat162float(h1));
            lov.y = pkbf(v2 - __bfloat162float(h2), v3 - __bfloat162float(h3));
            int sw = swz(pxl * 128 + c0 * 2);
            *(uint2*)(smemc + SM_BHI + sw) = hiv;
            *(uint2*)(smemc + SM_BLO + sw) = lov;
        }
        cpasync_wait_all();
        __syncthreads();

        const uint32_t Ahi = smem_base + SM_AHI, Alo = smem_base + SM_ALO;
        const uint32_t Bhi = smem_base + SM_BHI, Blo = smem_base + SM_BLO;
        #pragma unroll
        for (int ks = 0; ks < 4; ++ks) {
            uint32_t ah[2][4], al[2][4];
            ldsm4(ah[0], Ahi + aoff[ks]);
            ldsm4(ah[1], Ahi + aoff[ks] + 2048);
            ldsm4(al[0], Alo + aoff[ks]);
            ldsm4(al[1], Alo + aoff[ks] + 2048);
            #pragma unroll
            for (int nt = 0; nt < 4; ++nt) {
                uint32_t bh[4], bl[4];
                ldsm4(bh, Bhi + boff[ks] + nt * 2048);
                ldsm4(bl, Blo + boff[ks] + nt * 2048);
                #pragma unroll
                for (int mt = 0; mt < 2; ++mt) {
                    float* d0 = acc + (mt * 8 + nt * 2) * 4;
                    float* d1 = d0 + 4;
                    mma_bf16(d0, ah[mt], bh[0], bh[2]);
                    mma_bf16(d1, ah[mt], bh[1], bh[3]);
                    mma_bf16(d0, ah[mt], bl[0], bl[2]);
                    mma_bf16(d1, ah[mt], bl[1], bl[3]);
                    mma_bf16(d0, al[mt], bh[0], bh[2]);
                    mma_bf16(d1, al[mt], bh[1], bh[3]);
                }
            }
        }
    }

    const int row  = lane >> 2, colp = (lane & 3) * 2;
    float* outb = out + (size_t)b * CO * HW + base;
    #pragma unroll
    for (int mt = 0; mt < 2; ++mt) {
        int o0 = warp_m * 32 + mt * 16 + row;
        float b0 = bias[o0], b1 = bias[o0 + 8];
        #pragma unroll
        for (int n8 = 0; n8 < 8; ++n8) {
            const float* d = acc + (mt * 8 + n8) * 4;
            int pxo = warp_n * 64 + n8 * 8 + colp;
            *(float2*)(outb + (size_t)o0 * HW + pxo)       = make_float2(d[0] + b0, d[1] + b0);
            *(float2*)(outb + (size_t)(o0 + 8) * HW + pxo) = make_float2(d[2] + b1, d[3] + b1);
        }
    }
}

// ---------------------------------------------------------------------------
extern "C" void kernel_launch(void* const* d_in, const int* in_sizes, int n_in,
                              void* d_out, int out_size)
{
    const float* x   = (const float*)d_in[0];   // [8,64,96,96]
    const float* ow  = (const float*)d_in[1];   // [18,64,3,3]
    const float* ob  = (const float*)d_in[2];   // [18]
    const float* mw  = (const float*)d_in[3];   // [9,64,3,3]
    const float* mb  = (const float*)d_in[4];   // [9]
    const float* wgt = (const float*)d_in[5];   // [128,64,3,3]
    const float* bs  = (const float*)d_in[6];   // [128]
    float* out = (float*)d_out;                 // [8,128,96,96]

    cudaFuncSetAttribute(k_main, cudaFuncAttributeMaxDynamicSharedMemorySize, SM_TOTAL);

    k_wprep  <<<288, 256>>>(wgt);
    k_wprep2 <<<72, 256>>>(ow, mw);
    k_xt     <<<dim3(288, 2, 8), 256>>>(x);
    k_main   <<<dim3(72, 8), 256, SM_TOTAL>>>(ob, mb, bs, out);
}